// round 2
// baseline (speedup 1.0000x reference)
#include <cuda_runtime.h>
#include <math.h>

#define BB 2
#define TT 2048
#define DIM 1024
#define HID 4096
#define NH 16
#define KVH 4
#define HD 64
#define WIN 512
#define MROWS (BB*TT)   // 4096

// ---------------- scratch (static device memory; no allocations) ----------------
__device__ float g_xn[MROWS * DIM];
__device__ float g_q [MROWS * NH  * HD];
__device__ float g_k [MROWS * KVH * HD];
__device__ float g_v [MROWS * KVH * HD];
__device__ float g_y [MROWS * NH  * HD];
__device__ float g_h [MROWS * DIM];
__device__ float g_hn[MROWS * DIM];
__device__ float g_a1[MROWS * HID];
__device__ float g_g [MROWS * HID];

// ---------------- RMSNorm over DIM=1024 (one block per row) ----------------
__global__ __launch_bounds__(256) void rmsnorm_kernel(
    const float* __restrict__ x, const float* __restrict__ w,
    float* __restrict__ out, float eps)
{
    int row = blockIdx.x;
    int tid = threadIdx.x;  // 256 threads, 4 floats each
    const float4* xr = (const float4*)(x + (size_t)row * DIM);
    float4 xv = xr[tid];
    float acc = xv.x*xv.x + xv.y*xv.y + xv.z*xv.z + xv.w*xv.w;

    __shared__ float red[8];
    #pragma unroll
    for (int o = 16; o > 0; o >>= 1) acc += __shfl_xor_sync(0xffffffffu, acc, o);
    if ((tid & 31) == 0) red[tid >> 5] = acc;
    __syncthreads();
    if (tid < 8) {
        float a = red[tid];
        #pragma unroll
        for (int o = 4; o > 0; o >>= 1) a += __shfl_xor_sync(0xffu, a, o);
        if (tid == 0) red[0] = a;
    }
    __syncthreads();
    float r = rsqrtf(red[0] * (1.0f / DIM) + eps);

    float4 wv = ((const float4*)w)[tid];
    float4 ov;
    ov.x = xv.x * r * wv.x; ov.y = xv.y * r * wv.y;
    ov.z = xv.z * r * wv.z; ov.w = xv.w * r * wv.w;
    ((float4*)(out + (size_t)row * DIM))[tid] = ov;
}

// ---------------- per-head RMSNorm over HD=64 (one warp per vector) ----------------
__global__ __launch_bounds__(256) void headnorm_kernel(
    float* __restrict__ x, const float* __restrict__ w, int nvec)
{
    int vec = blockIdx.x * (blockDim.x >> 5) + (threadIdx.x >> 5);
    if (vec >= nvec) return;
    int lane = threadIdx.x & 31;
    float2* p = (float2*)(x + (size_t)vec * HD);
    float2 v = p[lane];
    float acc = v.x * v.x + v.y * v.y;
    #pragma unroll
    for (int o = 16; o > 0; o >>= 1) acc += __shfl_xor_sync(0xffffffffu, acc, o);
    float r = rsqrtf(acc * (1.0f / HD) + 1e-6f);
    float2 wv = ((const float2*)w)[lane];
    v.x *= r * wv.x; v.y *= r * wv.y;
    p[lane] = v;
}

// ---------------- SGEMM: C = A(MxK) @ W(NxK)^T, 128x128x8 tiles, 8x8/thread ----------------
// EPI 0: C = acc
// EPI 1: C = res + acc * scale[n]          (residual + layer scale)
// EPI 2: C = silu(other) * acc             (SwiGLU gate; other = w1 product)
template <int EPI>
__global__ __launch_bounds__(256) void sgemm_kernel(
    const float* __restrict__ A, const float* __restrict__ W, float* __restrict__ C,
    int M, int N, int K,
    const float* __restrict__ res, const float* __restrict__ scale,
    const float* __restrict__ other)
{
    __shared__ float As[8][128];
    __shared__ float Bs[8][128];

    int bm = blockIdx.y * 128;
    int bn = blockIdx.x * 128;
    int tid = threadIdx.x;

    int lrow = tid >> 1;            // 0..127
    int lc4  = (tid & 1) * 4;       // 0 or 4

    const float* Aptr = A + (size_t)(bm + lrow) * K + lc4;
    const float* Wptr = W + (size_t)(bn + lrow) * K + lc4;

    int tx = tid & 15;   // column group
    int ty = tid >> 4;   // row group

    float acc[8][8];
    #pragma unroll
    for (int i = 0; i < 8; i++)
        #pragma unroll
        for (int j = 0; j < 8; j++) acc[i][j] = 0.f;

    for (int k0 = 0; k0 < K; k0 += 8) {
        float4 av = *(const float4*)(Aptr + k0);
        float4 wv = *(const float4*)(Wptr + k0);
        As[lc4 + 0][lrow] = av.x; As[lc4 + 1][lrow] = av.y;
        As[lc4 + 2][lrow] = av.z; As[lc4 + 3][lrow] = av.w;
        Bs[lc4 + 0][lrow] = wv.x; Bs[lc4 + 1][lrow] = wv.y;
        Bs[lc4 + 2][lrow] = wv.z; Bs[lc4 + 3][lrow] = wv.w;
        __syncthreads();

        #pragma unroll
        for (int kk = 0; kk < 8; kk++) {
            float af[8], bf[8];
            #pragma unroll
            for (int i = 0; i < 4; i++) {
                float4 t = *(const float4*)&As[kk][ty * 8 + i * 4 - (i/1)*0];
                (void)t; // avoid misread; do explicit below
            }
            // explicit vector fragment loads
            {
                float4 a0 = *(const float4*)&As[kk][ty * 8];
                float4 a1 = *(const float4*)&As[kk][ty * 8 + 4];
                af[0]=a0.x; af[1]=a0.y; af[2]=a0.z; af[3]=a0.w;
                af[4]=a1.x; af[5]=a1.y; af[6]=a1.z; af[7]=a1.w;
                float4 b0 = *(const float4*)&Bs[kk][tx * 8];
                float4 b1 = *(const float4*)&Bs[kk][tx * 8 + 4];
                bf[0]=b0.x; bf[1]=b0.y; bf[2]=b0.z; bf[3]=b0.w;
                bf[4]=b1.x; bf[5]=b1.y; bf[6]=b1.z; bf[7]=b1.w;
            }
            #pragma unroll
            for (int i = 0; i < 8; i++)
                #pragma unroll
                for (int j = 0; j < 8; j++)
                    acc[i][j] += af[i] * bf[j];
        }
        __syncthreads();
    }

    // epilogue
    #pragma unroll
    for (int i = 0; i < 8; i++) {
        size_t m = bm + ty * 8 + i;
        size_t base = m * (size_t)N + bn + tx * 8;
        #pragma unroll
        for (int j = 0; j < 8; j++) {
            float v = acc[i][j];
            if (EPI == 1) {
                v = res[base + j] + v * scale[bn + tx * 8 + j];
            } else if (EPI == 2) {
                float a = other[base + j];
                v = (a / (1.f + expf(-a))) * v;
            }
            C[base + j] = v;
        }
    }
}

// ---------------- sliding-window causal attention (GQA), thread-per-query ----------------
// grid: (T/128, B*NH), block: 128. Flash-style online softmax, 32-key chunks.
__global__ __launch_bounds__(128) void attn_kernel(
    const float* __restrict__ q, const float* __restrict__ k,
    const float* __restrict__ v, float* __restrict__ y)
{
    int qt = blockIdx.x;
    int bh = blockIdx.y;
    int b = bh / NH, h = bh % NH;
    int kvh = h / (NH / KVH);
    int tid = threadIdx.x;
    int t = qt * 128 + tid;   // this thread's query index

    __shared__ float Ks[32][HD];
    __shared__ float Vs[32][HD];
    __shared__ float Ss[128][33];   // padded: bank = (tid + j) % 32, conflict-free

    const float sc = 0.125f;  // 1/sqrt(64)
    float qr[HD];
    const float* qp = q + ((size_t)(b * TT + t) * NH + h) * HD;
    #pragma unroll
    for (int d = 0; d < HD; d++) qr[d] = qp[d] * sc;

    float o[HD];
    #pragma unroll
    for (int d = 0; d < HD; d++) o[d] = 0.f;
    float mrun = -INFINITY, lrun = 0.f;

    int q0 = qt * 128;
    int kstart = max(0, q0 - WIN + 1) & ~31;
    int kend = q0 + 127;

    for (int kc = kstart; kc <= kend; kc += 32) {
        // cooperative load of K/V chunk (32 x 64), 4 float4 per thread each
        #pragma unroll
        for (int i = 0; i < 4; i++) {
            int f = tid + i * 128;          // float4 index, 0..511
            int r = f >> 4, c = f & 15;
            size_t grow = ((size_t)(b * TT + kc + r) * KVH + kvh) * HD;
            ((float4*)Ks)[f] = ((const float4*)(k + grow))[c];
            ((float4*)Vs)[f] = ((const float4*)(v + grow))[c];
        }
        __syncthreads();

        float cmax = -INFINITY;
        for (int j = 0; j < 32; j++) {
            int key = kc + j;
            float s = -INFINITY;
            if (key <= t && (t - key) < WIN) {
                s = 0.f;
                #pragma unroll
                for (int d = 0; d < HD; d++) s += qr[d] * Ks[j][d];
            }
            Ss[tid][j] = s;
            cmax = fmaxf(cmax, s);
        }

        float newm = fmaxf(mrun, cmax);
        if (newm > -INFINITY) {
            float corr = expf(mrun - newm);     // mrun = -inf -> 0
            lrun *= corr;
            #pragma unroll
            for (int d = 0; d < HD; d++) o[d] *= corr;
            for (int j = 0; j < 32; j++) {
                float p = expf(Ss[tid][j] - newm);  // -inf -> 0
                lrun += p;
                #pragma unroll
                for (int d = 0; d < HD; d++) o[d] += p * Vs[j][d];
            }
            mrun = newm;
        }
        __syncthreads();
    }

    float inv = 1.f / lrun;  // key==t always valid -> lrun > 0
    float* yp = y + ((size_t)(b * TT + t) * NH + h) * HD;
    #pragma unroll
    for (int d = 0; d < HD; d++) yp[d] = o[d] * inv;
}

// ---------------- launch ----------------
extern "C" void kernel_launch(void* const* d_in, const int* in_sizes, int n_in,
                              void* d_out, int out_size)
{
    const float* x            = (const float*)d_in[0];
    const float* wq           = (const float*)d_in[1];
    const float* wk           = (const float*)d_in[2];
    const float* wv           = (const float*)d_in[3];
    const float* wo           = (const float*)d_in[4];
    const float* w1           = (const float*)d_in[5];
    const float* w2           = (const float*)d_in[6];
    const float* w3           = (const float*)d_in[7];
    const float* q_norm_w     = (const float*)d_in[8];
    const float* k_norm_w     = (const float*)d_in[9];
    const float* attn_norm_w  = (const float*)d_in[10];
    const float* ffn_norm_w   = (const float*)d_in[11];
    const float* attn_scale   = (const float*)d_in[12];
    const float* ffn_scale    = (const float*)d_in[13];
    float* out = (float*)d_out;

    float *xn, *q, *k, *v, *y, *h, *hn, *a1, *g;
    cudaGetSymbolAddress((void**)&xn, g_xn);
    cudaGetSymbolAddress((void**)&q,  g_q);
    cudaGetSymbolAddress((void**)&k,  g_k);
    cudaGetSymbolAddress((void**)&v,  g_v);
    cudaGetSymbolAddress((void**)&y,  g_y);
    cudaGetSymbolAddress((void**)&h,  g_h);
    cudaGetSymbolAddress((void**)&hn, g_hn);
    cudaGetSymbolAddress((void**)&a1, g_a1);
    cudaGetSymbolAddress((void**)&g,  g_g);

    const int M = MROWS;

    // 1) attn pre-norm
    rmsnorm_kernel<<<M, 256>>>(x, attn_norm_w, xn, 1e-5f);

    // 2) QKV projections
    sgemm_kernel<0><<<dim3(NH*HD/128,  M/128), 256>>>(xn, wq, q, M, NH*HD,  DIM, nullptr, nullptr, nullptr);
    sgemm_kernel<0><<<dim3(KVH*HD/128, M/128), 256>>>(xn, wk, k, M, KVH*HD, DIM, nullptr, nullptr, nullptr);
    sgemm_kernel<0><<<dim3(KVH*HD/128, M/128), 256>>>(xn, wv, v, M, KVH*HD, DIM, nullptr, nullptr, nullptr);

    // 3) q/k head RMSNorm (warp per 64-vector)
    headnorm_kernel<<<(M * NH)  / 8, 256>>>(q, q_norm_w, M * NH);
    headnorm_kernel<<<(M * KVH) / 8, 256>>>(k, k_norm_w, M * KVH);

    // 4) sliding-window attention
    attn_kernel<<<dim3(TT / 128, BB * NH), 128>>>(q, k, v, y);

    // 5) output projection + residual + layer scale  -> h
    sgemm_kernel<1><<<dim3(DIM/128, M/128), 256>>>(y, wo, h, M, DIM, NH*HD, x, attn_scale, nullptr);

    // 6) ffn pre-norm
    rmsnorm_kernel<<<M, 256>>>(h, ffn_norm_w, hn, 1e-5f);

    // 7) SwiGLU FFN
    sgemm_kernel<0><<<dim3(HID/128, M/128), 256>>>(hn, w1, a1, M, HID, DIM, nullptr, nullptr, nullptr);
    sgemm_kernel<2><<<dim3(HID/128, M/128), 256>>>(hn, w3, g,  M, HID, DIM, nullptr, nullptr, a1);
    sgemm_kernel<1><<<dim3(DIM/128, M/128), 256>>>(g, w2, out, M, DIM, HID, h, ffn_scale, nullptr);
}

// round 3
// speedup vs baseline: 2.9546x; 2.9546x over previous
#include <cuda_runtime.h>
#include <cuda_bf16.h>
#include <math.h>

#define BB 2
#define TT 2048
#define DIM 1024
#define HID 4096
#define NH 16
#define KVH 4
#define HD 64
#define WIN 512
#define MROWS (BB*TT)   // 4096

// ---------------- scratch (static device memory; no allocations) ----------------
__device__ float g_xn[MROWS * DIM];
__device__ float g_q [MROWS * NH  * HD];
__device__ float g_k [MROWS * KVH * HD];
__device__ float g_v [MROWS * KVH * HD];
__device__ float g_y [MROWS * NH  * HD];
__device__ float g_h [MROWS * DIM];
__device__ float g_hn[MROWS * DIM];
__device__ float g_a1[MROWS * HID];
__device__ float g_g [MROWS * HID];

// ---------------- RMSNorm over DIM=1024 (one block per row) ----------------
__global__ __launch_bounds__(256) void rmsnorm_kernel(
    const float* __restrict__ x, const float* __restrict__ w,
    float* __restrict__ out, float eps)
{
    int row = blockIdx.x;
    int tid = threadIdx.x;  // 256 threads, 4 floats each
    const float4* xr = (const float4*)(x + (size_t)row * DIM);
    float4 xv = xr[tid];
    float acc = xv.x*xv.x + xv.y*xv.y + xv.z*xv.z + xv.w*xv.w;

    __shared__ float red[8];
    #pragma unroll
    for (int o = 16; o > 0; o >>= 1) acc += __shfl_xor_sync(0xffffffffu, acc, o);
    if ((tid & 31) == 0) red[tid >> 5] = acc;
    __syncthreads();
    if (tid < 8) {
        float a = red[tid];
        #pragma unroll
        for (int o = 4; o > 0; o >>= 1) a += __shfl_xor_sync(0xffu, a, o);
        if (tid == 0) red[0] = a;
    }
    __syncthreads();
    float r = rsqrtf(red[0] * (1.0f / DIM) + eps);

    float4 wv = ((const float4*)w)[tid];
    float4 ov;
    ov.x = xv.x * r * wv.x; ov.y = xv.y * r * wv.y;
    ov.z = xv.z * r * wv.z; ov.w = xv.w * r * wv.w;
    ((float4*)(out + (size_t)row * DIM))[tid] = ov;
}

// ---------------- per-head RMSNorm over HD=64 (one warp per vector) ----------------
__global__ __launch_bounds__(256) void headnorm_kernel(
    float* __restrict__ x, const float* __restrict__ w, int nvec)
{
    int vec = blockIdx.x * (blockDim.x >> 5) + (threadIdx.x >> 5);
    if (vec >= nvec) return;
    int lane = threadIdx.x & 31;
    float2* p = (float2*)(x + (size_t)vec * HD);
    float2 v = p[lane];
    float acc = v.x * v.x + v.y * v.y;
    #pragma unroll
    for (int o = 16; o > 0; o >>= 1) acc += __shfl_xor_sync(0xffffffffu, acc, o);
    float r = rsqrtf(acc * (1.0f / HD) + 1e-6f);
    float2 wv = ((const float2*)w)[lane];
    v.x *= r * wv.x; v.y *= r * wv.y;
    p[lane] = v;
}

// ---------------- bf16 tensor-core GEMM: C = A(MxK) @ W(NxK)^T ----------------
// 128x128x32 block tile, 8 warps (2 in M x 4 in N), 64x32 warp tile.
// mma.sync.aligned.m16n8k16.row.col.f32.bf16.bf16.f32, fp32 accumulate.
// EPI 0: C = acc
// EPI 1: C = res + acc * scale[n]
// EPI 2: C = silu(other) * acc
#define GP 40      // smem row pitch in bf16 elements (conflict-free: 20 words/row)

__device__ __forceinline__ uint2 pack_bf16x4(float4 v) {
    __nv_bfloat162 lo = __floats2bfloat162_rn(v.x, v.y);
    __nv_bfloat162 hi = __floats2bfloat162_rn(v.z, v.w);
    uint2 r;
    r.x = *(unsigned int*)&lo;
    r.y = *(unsigned int*)&hi;
    return r;
}

template <int EPI>
__global__ __launch_bounds__(256) void gemm_bf16_kernel(
    const float* __restrict__ A, const float* __restrict__ W, float* __restrict__ C,
    int M, int N, int K,
    const float* __restrict__ res, const float* __restrict__ scale,
    const float* __restrict__ other)
{
    __shared__ __nv_bfloat16 As[2][128 * GP];
    __shared__ __nv_bfloat16 Bs[2][128 * GP];

    const int bm = blockIdx.y * 128;
    const int bn = blockIdx.x * 128;
    const int tid = threadIdx.x;
    const int warpId = tid >> 5;
    const int lane = tid & 31;
    const int gid = lane >> 2;    // groupID
    const int tg  = lane & 3;     // threadID_in_group
    const int warpM = warpId & 1;     // 0..1
    const int warpN = warpId >> 1;    // 0..3

    float acc[4][4][4];
    #pragma unroll
    for (int mi = 0; mi < 4; mi++)
        #pragma unroll
        for (int ni = 0; ni < 4; ni++)
            #pragma unroll
            for (int c = 0; c < 4; c++) acc[mi][ni][c] = 0.f;

    const int iters = K >> 5;   // K / 32
    float4 pa[4], pb[4];

    // prologue: fetch + stage tile 0
    #pragma unroll
    for (int i = 0; i < 4; i++) {
        int f = tid + i * 256;
        int row = f >> 3, q = f & 7;
        pa[i] = *(const float4*)(A + (size_t)(bm + row) * K + q * 4);
        pb[i] = *(const float4*)(W + (size_t)(bn + row) * K + q * 4);
    }
    #pragma unroll
    for (int i = 0; i < 4; i++) {
        int f = tid + i * 256;
        int row = f >> 3, q = f & 7;
        ((uint2*)As[0])[row * 10 + q] = pack_bf16x4(pa[i]);
        ((uint2*)Bs[0])[row * 10 + q] = pack_bf16x4(pb[i]);
    }
    __syncthreads();

    for (int it = 0; it < iters; ++it) {
        int nxt = it + 1;
        if (nxt < iters) {
            int k0 = nxt << 5;
            #pragma unroll
            for (int i = 0; i < 4; i++) {
                int f = tid + i * 256;
                int row = f >> 3, q = f & 7;
                pa[i] = *(const float4*)(A + (size_t)(bm + row) * K + k0 + q * 4);
                pb[i] = *(const float4*)(W + (size_t)(bn + row) * K + k0 + q * 4);
            }
        }

        // compute on buffer it&1
        {
            const unsigned int* as = (const unsigned int*)As[it & 1];
            const unsigned int* bs = (const unsigned int*)Bs[it & 1];
            #pragma unroll
            for (int ks = 0; ks < 2; ks++) {
                unsigned int af[4][4], bfr[4][2];
                #pragma unroll
                for (int mi = 0; mi < 4; mi++) {
                    int r = warpM * 64 + mi * 16 + gid;
                    int w0 = r * 20 + ks * 8 + tg;
                    int w1 = (r + 8) * 20 + ks * 8 + tg;
                    af[mi][0] = as[w0];
                    af[mi][1] = as[w1];
                    af[mi][2] = as[w0 + 4];
                    af[mi][3] = as[w1 + 4];
                }
                #pragma unroll
                for (int ni = 0; ni < 4; ni++) {
                    int cidx = warpN * 32 + ni * 8 + gid;
                    int w0 = cidx * 20 + ks * 8 + tg;
                    bfr[ni][0] = bs[w0];
                    bfr[ni][1] = bs[w0 + 4];
                }
                #pragma unroll
                for (int mi = 0; mi < 4; mi++)
                    #pragma unroll
                    for (int ni = 0; ni < 4; ni++) {
                        asm volatile(
                            "mma.sync.aligned.m16n8k16.row.col.f32.bf16.bf16.f32 "
                            "{%0,%1,%2,%3}, {%4,%5,%6,%7}, {%8,%9}, {%0,%1,%2,%3};"
                            : "+f"(acc[mi][ni][0]), "+f"(acc[mi][ni][1]),
                              "+f"(acc[mi][ni][2]), "+f"(acc[mi][ni][3])
                            : "r"(af[mi][0]), "r"(af[mi][1]), "r"(af[mi][2]), "r"(af[mi][3]),
                              "r"(bfr[ni][0]), "r"(bfr[ni][1]));
                    }
            }
        }

        if (nxt < iters) {
            #pragma unroll
            for (int i = 0; i < 4; i++) {
                int f = tid + i * 256;
                int row = f >> 3, q = f & 7;
                ((uint2*)As[nxt & 1])[row * 10 + q] = pack_bf16x4(pa[i]);
                ((uint2*)Bs[nxt & 1])[row * 10 + q] = pack_bf16x4(pb[i]);
            }
        }
        __syncthreads();
    }

    // epilogue
    #pragma unroll
    for (int mi = 0; mi < 4; mi++) {
        #pragma unroll
        for (int ni = 0; ni < 4; ni++) {
            int m0 = bm + warpM * 64 + mi * 16 + gid;
            int n0 = bn + warpN * 32 + ni * 8 + tg * 2;
            #pragma unroll
            for (int half = 0; half < 2; half++) {
                int m = m0 + half * 8;
                size_t base = (size_t)m * N + n0;
                float v0 = acc[mi][ni][half * 2 + 0];
                float v1 = acc[mi][ni][half * 2 + 1];
                if (EPI == 1) {
                    v0 = res[base + 0] + v0 * scale[n0 + 0];
                    v1 = res[base + 1] + v1 * scale[n0 + 1];
                } else if (EPI == 2) {
                    float a0 = other[base + 0];
                    float a1 = other[base + 1];
                    v0 = (a0 / (1.f + __expf(-a0))) * v0;
                    v1 = (a1 / (1.f + __expf(-a1))) * v1;
                }
                float2 ov; ov.x = v0; ov.y = v1;
                *(float2*)(C + base) = ov;
            }
        }
    }
}

// ---------------- sliding-window causal attention (GQA), thread-per-query ----------------
__global__ __launch_bounds__(128) void attn_kernel(
    const float* __restrict__ q, const float* __restrict__ k,
    const float* __restrict__ v, float* __restrict__ y)
{
    int qt = blockIdx.x;
    int bh = blockIdx.y;
    int b = bh / NH, h = bh % NH;
    int kvh = h / (NH / KVH);
    int tid = threadIdx.x;
    int t = qt * 128 + tid;   // this thread's query index

    __shared__ float Ks[32][HD];
    __shared__ float Vs[32][HD];
    __shared__ float Ss[128][33];

    const float sc = 0.125f;  // 1/sqrt(64)
    float qr[HD];
    const float* qp = q + ((size_t)(b * TT + t) * NH + h) * HD;
    #pragma unroll
    for (int d = 0; d < HD; d++) qr[d] = qp[d] * sc;

    float o[HD];
    #pragma unroll
    for (int d = 0; d < HD; d++) o[d] = 0.f;
    float mrun = -INFINITY, lrun = 0.f;

    int q0 = qt * 128;
    int kstart = max(0, q0 - WIN + 1) & ~31;
    int kend = q0 + 127;

    for (int kc = kstart; kc <= kend; kc += 32) {
        #pragma unroll
        for (int i = 0; i < 4; i++) {
            int f = tid + i * 128;
            int r = f >> 4, c = f & 15;
            size_t grow = ((size_t)(b * TT + kc + r) * KVH + kvh) * HD;
            ((float4*)Ks)[f] = ((const float4*)(k + grow))[c];
            ((float4*)Vs)[f] = ((const float4*)(v + grow))[c];
        }
        __syncthreads();

        float cmax = -INFINITY;
        for (int j = 0; j < 32; j++) {
            int key = kc + j;
            float s = -INFINITY;
            if (key <= t && (t - key) < WIN) {
                s = 0.f;
                #pragma unroll
                for (int d = 0; d < HD; d++) s += qr[d] * Ks[j][d];
            }
            Ss[tid][j] = s;
            cmax = fmaxf(cmax, s);
        }

        float newm = fmaxf(mrun, cmax);
        if (newm > -INFINITY) {
            float corr = __expf(mrun - newm);
            lrun *= corr;
            #pragma unroll
            for (int d = 0; d < HD; d++) o[d] *= corr;
            for (int j = 0; j < 32; j++) {
                float p = __expf(Ss[tid][j] - newm);
                lrun += p;
                #pragma unroll
                for (int d = 0; d < HD; d++) o[d] += p * Vs[j][d];
            }
            mrun = newm;
        }
        __syncthreads();
    }

    float inv = 1.f / lrun;
    float* yp = y + ((size_t)(b * TT + t) * NH + h) * HD;
    #pragma unroll
    for (int d = 0; d < HD; d++) yp[d] = o[d] * inv;
}

// ---------------- launch ----------------
extern "C" void kernel_launch(void* const* d_in, const int* in_sizes, int n_in,
                              void* d_out, int out_size)
{
    const float* x            = (const float*)d_in[0];
    const float* wq           = (const float*)d_in[1];
    const float* wk           = (const float*)d_in[2];
    const float* wv           = (const float*)d_in[3];
    const float* wo           = (const float*)d_in[4];
    const float* w1           = (const float*)d_in[5];
    const float* w2           = (const float*)d_in[6];
    const float* w3           = (const float*)d_in[7];
    const float* q_norm_w     = (const float*)d_in[8];
    const float* k_norm_w     = (const float*)d_in[9];
    const float* attn_norm_w  = (const float*)d_in[10];
    const float* ffn_norm_w   = (const float*)d_in[11];
    const float* attn_scale   = (const float*)d_in[12];
    const float* ffn_scale    = (const float*)d_in[13];
    float* out = (float*)d_out;

    float *xn, *q, *k, *v, *y, *h, *hn, *a1, *g;
    cudaGetSymbolAddress((void**)&xn, g_xn);
    cudaGetSymbolAddress((void**)&q,  g_q);
    cudaGetSymbolAddress((void**)&k,  g_k);
    cudaGetSymbolAddress((void**)&v,  g_v);
    cudaGetSymbolAddress((void**)&y,  g_y);
    cudaGetSymbolAddress((void**)&h,  g_h);
    cudaGetSymbolAddress((void**)&hn, g_hn);
    cudaGetSymbolAddress((void**)&a1, g_a1);
    cudaGetSymbolAddress((void**)&g,  g_g);

    const int M = MROWS;

    // 1) attn pre-norm
    rmsnorm_kernel<<<M, 256>>>(x, attn_norm_w, xn, 1e-5f);

    // 2) QKV projections (bf16 tensor cores)
    gemm_bf16_kernel<0><<<dim3(NH*HD/128,  M/128), 256>>>(xn, wq, q, M, NH*HD,  DIM, nullptr, nullptr, nullptr);
    gemm_bf16_kernel<0><<<dim3(KVH*HD/128, M/128), 256>>>(xn, wk, k, M, KVH*HD, DIM, nullptr, nullptr, nullptr);
    gemm_bf16_kernel<0><<<dim3(KVH*HD/128, M/128), 256>>>(xn, wv, v, M, KVH*HD, DIM, nullptr, nullptr, nullptr);

    // 3) q/k head RMSNorm
    headnorm_kernel<<<(M * NH)  / 8, 256>>>(q, q_norm_w, M * NH);
    headnorm_kernel<<<(M * KVH) / 8, 256>>>(k, k_norm_w, M * KVH);

    // 4) sliding-window attention
    attn_kernel<<<dim3(TT / 128, BB * NH), 128>>>(q, k, v, y);

    // 5) output projection + residual + layer scale  -> h
    gemm_bf16_kernel<1><<<dim3(DIM/128, M/128), 256>>>(y, wo, h, M, DIM, NH*HD, x, attn_scale, nullptr);

    // 6) ffn pre-norm
    rmsnorm_kernel<<<M, 256>>>(h, ffn_norm_w, hn, 1e-5f);

    // 7) SwiGLU FFN
    gemm_bf16_kernel<0><<<dim3(HID/128, M/128), 256>>>(hn, w1, a1, M, HID, DIM, nullptr, nullptr, nullptr);
    gemm_bf16_kernel<2><<<dim3(HID/128, M/128), 256>>>(hn, w3, g,  M, HID, DIM, nullptr, nullptr, a1);
    gemm_bf16_kernel<1><<<dim3(DIM/128, M/128), 256>>>(g, w2, out, M, DIM, HID, h, ffn_scale, nullptr);
}

// round 4
// speedup vs baseline: 4.3166x; 1.4610x over previous
#include <cuda_runtime.h>
#include <cuda_bf16.h>
#include <math.h>

#define BB 2
#define TT 2048
#define DIM 1024
#define HID 4096
#define NH 16
#define KVH 4
#define HD 64
#define WIN 512
#define MROWS (BB*TT)       // 4096
#define QKVN 1536           // NH*HD + 2*KVH*HD

// ---------------- scratch (static device memory; no allocations) ----------------
__device__ __nv_bfloat16 g_xnb[MROWS * DIM];
__device__ float         g_qkv[MROWS * QKVN];
__device__ __nv_bfloat16 g_yb [MROWS * NH * HD];
__device__ float         g_h  [MROWS * DIM];
__device__ __nv_bfloat16 g_hnb[MROWS * DIM];
__device__ float         g_a1 [MROWS * HID];
__device__ __nv_bfloat16 g_gb [MROWS * HID];
// bf16 weight mirrors
__device__ __nv_bfloat16 g_wqkv[QKVN * DIM];
__device__ __nv_bfloat16 g_wob [DIM * NH * HD];
__device__ __nv_bfloat16 g_w1b [HID * DIM];
__device__ __nv_bfloat16 g_w3b [HID * DIM];
__device__ __nv_bfloat16 g_w2b [DIM * HID];

// ---------------- fp32 -> bf16 convert (vectorized) ----------------
__global__ __launch_bounds__(256) void f2bf_kernel(
    const float* __restrict__ s, __nv_bfloat16* __restrict__ d, int n4)
{
    int i = blockIdx.x * 256 + threadIdx.x;
    if (i < n4) {
        float4 v = ((const float4*)s)[i];
        __nv_bfloat162 lo = __floats2bfloat162_rn(v.x, v.y);
        __nv_bfloat162 hi = __floats2bfloat162_rn(v.z, v.w);
        uint2 r; r.x = *(unsigned*)&lo; r.y = *(unsigned*)&hi;
        ((uint2*)d)[i] = r;
    }
}

// ---------------- RMSNorm over DIM=1024, bf16 output ----------------
__global__ __launch_bounds__(256) void rmsnorm_kernel(
    const float* __restrict__ x, const float* __restrict__ w,
    __nv_bfloat16* __restrict__ out, float eps)
{
    int row = blockIdx.x;
    int tid = threadIdx.x;
    const float4* xr = (const float4*)(x + (size_t)row * DIM);
    float4 xv = xr[tid];
    float acc = xv.x*xv.x + xv.y*xv.y + xv.z*xv.z + xv.w*xv.w;

    __shared__ float red[8];
    #pragma unroll
    for (int o = 16; o > 0; o >>= 1) acc += __shfl_xor_sync(0xffffffffu, acc, o);
    if ((tid & 31) == 0) red[tid >> 5] = acc;
    __syncthreads();
    if (tid < 8) {
        float a = red[tid];
        #pragma unroll
        for (int o = 4; o > 0; o >>= 1) a += __shfl_xor_sync(0xffu, a, o);
        if (tid == 0) red[0] = a;
    }
    __syncthreads();
    float r = rsqrtf(red[0] * (1.0f / DIM) + eps);

    float4 wv = ((const float4*)w)[tid];
    __nv_bfloat162 lo = __floats2bfloat162_rn(xv.x * r * wv.x, xv.y * r * wv.y);
    __nv_bfloat162 hi = __floats2bfloat162_rn(xv.z * r * wv.z, xv.w * r * wv.w);
    uint2 ov; ov.x = *(unsigned*)&lo; ov.y = *(unsigned*)&hi;
    ((uint2*)(out + (size_t)row * DIM))[tid] = ov;
}

// ---------------- per-head RMSNorm over HD=64 (warp per vector), strided ----------------
__global__ __launch_bounds__(256) void headnorm_kernel(
    float* __restrict__ base, const float* __restrict__ w,
    int rowStride, int nh, int nvec)
{
    int vec = blockIdx.x * (blockDim.x >> 5) + (threadIdx.x >> 5);
    if (vec >= nvec) return;
    int lane = threadIdx.x & 31;
    int row = vec / nh, hh = vec % nh;
    float2* p = (float2*)(base + (size_t)row * rowStride + hh * HD);
    float2 v = p[lane];
    float acc = v.x * v.x + v.y * v.y;
    #pragma unroll
    for (int o = 16; o > 0; o >>= 1) acc += __shfl_xor_sync(0xffffffffu, acc, o);
    float r = rsqrtf(acc * (1.0f / HD) + 1e-6f);
    float2 wv = ((const float2*)w)[lane];
    v.x *= r * wv.x; v.y *= r * wv.y;
    p[lane] = v;
}

// ---------------- bf16 tensor-core GEMM, cp.async 3-stage pipeline ----------------
// C = A(MxK bf16) @ W(NxK bf16)^T ; 128x128x64 block tile, 8 warps (2M x 4N), 64x32 warp tile.
// EPI 0: C(fp32) = acc
// EPI 1: C(fp32) = res + acc * scale[n]
// EPI 2: C(bf16) = silu(other) * acc
#define STAGES 3
#define KT 64
#define PITCHB 144                 // bytes per smem row (72 bf16, conflict-free)
#define PITCHW 36                  // words per smem row
#define OPBYTES (128 * PITCHB)     // 18432 per operand per stage
#define STAGE_BYTES (2 * OPBYTES)  // 36864
#define GSMEM (STAGES * STAGE_BYTES)

__device__ __forceinline__ void cp16(unsigned saddr, const void* g) {
    asm volatile("cp.async.cg.shared.global [%0], [%1], 16;\n" :: "r"(saddr), "l"(g));
}

template <int EPI>
__global__ __launch_bounds__(256) void gemm_kernel(
    const __nv_bfloat16* __restrict__ A, const __nv_bfloat16* __restrict__ W,
    void* __restrict__ Cv, int M, int N, int K,
    const float* __restrict__ res, const float* __restrict__ scale,
    const float* __restrict__ other)
{
    extern __shared__ char smem[];
    const int bm = blockIdx.y * 128;
    const int bn = blockIdx.x * 128;
    const int tid = threadIdx.x;
    const int warpId = tid >> 5, lane = tid & 31;
    const int gid = lane >> 2, tg = lane & 3;
    const int warpM = warpId & 1, warpN = warpId >> 1;

    const unsigned sbase = (unsigned)__cvta_generic_to_shared(smem);
    const int ktiles = K >> 6;

    float acc[4][4][4];
    #pragma unroll
    for (int mi = 0; mi < 4; mi++)
        #pragma unroll
        for (int ni = 0; ni < 4; ni++)
            #pragma unroll
            for (int c = 0; c < 4; c++) acc[mi][ni][c] = 0.f;

    // fetch one 128x64 A tile + 128x64 B tile into stage s (guarded)
    auto fetch = [&](int s, int kt) {
        if (kt < ktiles) {
            unsigned sa = sbase + s * STAGE_BYTES;
            unsigned sb = sa + OPBYTES;
            #pragma unroll
            for (int i = 0; i < 4; i++) {
                int chunk = tid + i * 256;         // 0..1023
                int row = chunk >> 3, c = chunk & 7;
                size_t go = (size_t)row * K + (size_t)kt * KT + c * 8;
                cp16(sa + row * PITCHB + c * 16, A + (size_t)bm * K + go);
                cp16(sb + row * PITCHB + c * 16, W + (size_t)bn * K + go);
            }
        }
    };

    fetch(0, 0);
    asm volatile("cp.async.commit_group;\n" ::: "memory");
    fetch(1, 1);
    asm volatile("cp.async.commit_group;\n" ::: "memory");

    for (int kt = 0; kt < ktiles; kt++) {
        asm volatile("cp.async.wait_group 1;\n" ::: "memory");
        __syncthreads();

        fetch((kt + 2) % STAGES, kt + 2);
        asm volatile("cp.async.commit_group;\n" ::: "memory");

        const int st = kt % STAGES;
        const unsigned* as = (const unsigned*)(smem + st * STAGE_BYTES);
        const unsigned* bs = (const unsigned*)(smem + st * STAGE_BYTES + OPBYTES);

        #pragma unroll
        for (int ks = 0; ks < 4; ks++) {
            unsigned af[4][4], bfr[4][2];
            #pragma unroll
            for (int mi = 0; mi < 4; mi++) {
                int r = warpM * 64 + mi * 16 + gid;
                int w0 = r * PITCHW + ks * 8 + tg;
                int w1 = (r + 8) * PITCHW + ks * 8 + tg;
                af[mi][0] = as[w0];
                af[mi][1] = as[w1];
                af[mi][2] = as[w0 + 4];
                af[mi][3] = as[w1 + 4];
            }
            #pragma unroll
            for (int ni = 0; ni < 4; ni++) {
                int cidx = warpN * 32 + ni * 8 + gid;
                int w0 = cidx * PITCHW + ks * 8 + tg;
                bfr[ni][0] = bs[w0];
                bfr[ni][1] = bs[w0 + 4];
            }
            #pragma unroll
            for (int mi = 0; mi < 4; mi++)
                #pragma unroll
                for (int ni = 0; ni < 4; ni++) {
                    asm volatile(
                        "mma.sync.aligned.m16n8k16.row.col.f32.bf16.bf16.f32 "
                        "{%0,%1,%2,%3}, {%4,%5,%6,%7}, {%8,%9}, {%0,%1,%2,%3};"
                        : "+f"(acc[mi][ni][0]), "+f"(acc[mi][ni][1]),
                          "+f"(acc[mi][ni][2]), "+f"(acc[mi][ni][3])
                        : "r"(af[mi][0]), "r"(af[mi][1]), "r"(af[mi][2]), "r"(af[mi][3]),
                          "r"(bfr[ni][0]), "r"(bfr[ni][1]));
                }
        }
    }

    // epilogue
    #pragma unroll
    for (int mi = 0; mi < 4; mi++) {
        #pragma unroll
        for (int ni = 0; ni < 4; ni++) {
            int m0 = bm + warpM * 64 + mi * 16 + gid;
            int n0 = bn + warpN * 32 + ni * 8 + tg * 2;
            #pragma unroll
            for (int half = 0; half < 2; half++) {
                int m = m0 + half * 8;
                size_t base = (size_t)m * N + n0;
                float v0 = acc[mi][ni][half * 2 + 0];
                float v1 = acc[mi][ni][half * 2 + 1];
                if (EPI == 0) {
                    float2 ov; ov.x = v0; ov.y = v1;
                    *(float2*)((float*)Cv + base) = ov;
                } else if (EPI == 1) {
                    v0 = res[base + 0] + v0 * scale[n0 + 0];
                    v1 = res[base + 1] + v1 * scale[n0 + 1];
                    float2 ov; ov.x = v0; ov.y = v1;
                    *(float2*)((float*)Cv + base) = ov;
                } else {
                    float a0 = other[base + 0];
                    float a1 = other[base + 1];
                    v0 = (a0 / (1.f + __expf(-a0))) * v0;
                    v1 = (a1 / (1.f + __expf(-a1))) * v1;
                    __nv_bfloat162 p = __floats2bfloat162_rn(v0, v1);
                    *(__nv_bfloat162*)((__nv_bfloat16*)Cv + base) = p;
                }
            }
        }
    }
}

// ---------------- sliding-window causal attention (GQA), thread-per-query ----------------
// reads fused qkv fp32 buffer (row stride QKVN), writes bf16 y.
__global__ __launch_bounds__(128) void attn_kernel(
    const float* __restrict__ qkv, __nv_bfloat16* __restrict__ y)
{
    int qt = blockIdx.x;
    int bh = blockIdx.y;
    int b = bh / NH, h = bh % NH;
    int kvh = h / (NH / KVH);
    int tid = threadIdx.x;
    int t = qt * 128 + tid;

    __shared__ float Ks[32][HD];
    __shared__ float Vs[32][HD];
    __shared__ float Ss[128][33];

    const float sc = 0.125f;
    float qr[HD];
    const float* qp = qkv + (size_t)(b * TT + t) * QKVN + h * HD;
    #pragma unroll
    for (int d = 0; d < HD; d++) qr[d] = qp[d] * sc;

    float o[HD];
    #pragma unroll
    for (int d = 0; d < HD; d++) o[d] = 0.f;
    float mrun = -INFINITY, lrun = 0.f;

    int q0 = qt * 128;
    int kstart = max(0, q0 - WIN + 1) & ~31;
    int kend = q0 + 127;

    for (int kc = kstart; kc <= kend; kc += 32) {
        #pragma unroll
        for (int i = 0; i < 4; i++) {
            int f = tid + i * 128;
            int r = f >> 4, c = f & 15;
            size_t grow = (size_t)(b * TT + kc + r) * QKVN + NH * HD + kvh * HD;
            ((float4*)Ks)[f] = ((const float4*)(qkv + grow))[c];
            ((float4*)Vs)[f] = ((const float4*)(qkv + grow + KVH * HD))[c];
        }
        __syncthreads();

        float cmax = -INFINITY;
        for (int j = 0; j < 32; j++) {
            int key = kc + j;
            float s = -INFINITY;
            if (key <= t && (t - key) < WIN) {
                s = 0.f;
                #pragma unroll
                for (int d = 0; d < HD; d++) s += qr[d] * Ks[j][d];
            }
            Ss[tid][j] = s;
            cmax = fmaxf(cmax, s);
        }

        float newm = fmaxf(mrun, cmax);
        if (newm > -INFINITY) {
            float corr = __expf(mrun - newm);
            lrun *= corr;
            #pragma unroll
            for (int d = 0; d < HD; d++) o[d] *= corr;
            for (int j = 0; j < 32; j++) {
                float p = __expf(Ss[tid][j] - newm);
                lrun += p;
                #pragma unroll
                for (int d = 0; d < HD; d++) o[d] += p * Vs[j][d];
            }
            mrun = newm;
        }
        __syncthreads();
    }

    float inv = 1.f / lrun;
    __nv_bfloat16* yp = y + ((size_t)(b * TT + t) * NH + h) * HD;
    #pragma unroll
    for (int d = 0; d < HD; d += 2) {
        __nv_bfloat162 p = __floats2bfloat162_rn(o[d] * inv, o[d + 1] * inv);
        *(__nv_bfloat162*)(yp + d) = p;
    }
}

// ---------------- launch ----------------
extern "C" void kernel_launch(void* const* d_in, const int* in_sizes, int n_in,
                              void* d_out, int out_size)
{
    const float* x            = (const float*)d_in[0];
    const float* wq           = (const float*)d_in[1];
    const float* wk           = (const float*)d_in[2];
    const float* wv           = (const float*)d_in[3];
    const float* wo           = (const float*)d_in[4];
    const float* w1           = (const float*)d_in[5];
    const float* w2           = (const float*)d_in[6];
    const float* w3           = (const float*)d_in[7];
    const float* q_norm_w     = (const float*)d_in[8];
    const float* k_norm_w     = (const float*)d_in[9];
    const float* attn_norm_w  = (const float*)d_in[10];
    const float* ffn_norm_w   = (const float*)d_in[11];
    const float* attn_scale   = (const float*)d_in[12];
    const float* ffn_scale    = (const float*)d_in[13];
    float* out = (float*)d_out;

    __nv_bfloat16 *xnb, *yb, *hnb, *gb, *wqkv, *wob, *w1b, *w3b, *w2b;
    float *qkv, *h, *a1;
    cudaGetSymbolAddress((void**)&xnb,  g_xnb);
    cudaGetSymbolAddress((void**)&qkv,  g_qkv);
    cudaGetSymbolAddress((void**)&yb,   g_yb);
    cudaGetSymbolAddress((void**)&h,    g_h);
    cudaGetSymbolAddress((void**)&hnb,  g_hnb);
    cudaGetSymbolAddress((void**)&a1,   g_a1);
    cudaGetSymbolAddress((void**)&gb,   g_gb);
    cudaGetSymbolAddress((void**)&wqkv, g_wqkv);
    cudaGetSymbolAddress((void**)&wob,  g_wob);
    cudaGetSymbolAddress((void**)&w1b,  g_w1b);
    cudaGetSymbolAddress((void**)&w3b,  g_w3b);
    cudaGetSymbolAddress((void**)&w2b,  g_w2b);

    const int M = MROWS;
    const int smem_bytes = GSMEM;
    cudaFuncSetAttribute(gemm_kernel<0>, cudaFuncAttributeMaxDynamicSharedMemorySize, smem_bytes);
    cudaFuncSetAttribute(gemm_kernel<1>, cudaFuncAttributeMaxDynamicSharedMemorySize, smem_bytes);
    cudaFuncSetAttribute(gemm_kernel<2>, cudaFuncAttributeMaxDynamicSharedMemorySize, smem_bytes);

    // 0) weight conversions to bf16 (wqkv fused: rows [wq | wk | wv])
    f2bf_kernel<<<(NH*HD*DIM)/4/256,  256>>>(wq, wqkv,                  (NH*HD*DIM)/4);
    f2bf_kernel<<<(KVH*HD*DIM)/4/256, 256>>>(wk, wqkv + NH*HD*DIM,      (KVH*HD*DIM)/4);
    f2bf_kernel<<<(KVH*HD*DIM)/4/256, 256>>>(wv, wqkv + (NH+KVH)*HD*DIM,(KVH*HD*DIM)/4);
    f2bf_kernel<<<(DIM*NH*HD)/4/256,  256>>>(wo, wob, (DIM*NH*HD)/4);
    f2bf_kernel<<<(HID*DIM)/4/256,    256>>>(w1, w1b, (HID*DIM)/4);
    f2bf_kernel<<<(HID*DIM)/4/256,    256>>>(w3, w3b, (HID*DIM)/4);
    f2bf_kernel<<<(DIM*HID)/4/256,    256>>>(w2, w2b, (DIM*HID)/4);

    // 1) attn pre-norm -> bf16
    rmsnorm_kernel<<<M, 256>>>(x, attn_norm_w, xnb, 1e-5f);

    // 2) fused QKV projection (fp32 out)
    gemm_kernel<0><<<dim3(QKVN/128, M/128), 256, smem_bytes>>>(
        xnb, wqkv, qkv, M, QKVN, DIM, nullptr, nullptr, nullptr);

    // 3) q/k head RMSNorm (in-place on fused buffer)
    headnorm_kernel<<<(M * NH)  / 8, 256>>>(qkv,           q_norm_w, QKVN, NH,  M * NH);
    headnorm_kernel<<<(M * KVH) / 8, 256>>>(qkv + NH * HD, k_norm_w, QKVN, KVH, M * KVH);

    // 4) sliding-window attention -> bf16 y
    attn_kernel<<<dim3(TT / 128, BB * NH), 128>>>(qkv, yb);

    // 5) output projection + residual + layer scale -> h (fp32)
    gemm_kernel<1><<<dim3(DIM/128, M/128), 256, smem_bytes>>>(
        yb, wob, h, M, DIM, NH*HD, x, attn_scale, nullptr);

    // 6) ffn pre-norm -> bf16
    rmsnorm_kernel<<<M, 256>>>(h, ffn_norm_w, hnb, 1e-5f);

    // 7) SwiGLU FFN
    gemm_kernel<0><<<dim3(HID/128, M/128), 256, smem_bytes>>>(
        hnb, w1b, a1, M, HID, DIM, nullptr, nullptr, nullptr);
    gemm_kernel<2><<<dim3(HID/128, M/128), 256, smem_bytes>>>(
        hnb, w3b, gb, M, HID, DIM, nullptr, nullptr, a1);
    gemm_kernel<1><<<dim3(DIM/128, M/128), 256, smem_bytes>>>(
        gb, w2b, out, M, DIM, HID, h, ffn_scale, nullptr);
}

// round 5
// speedup vs baseline: 7.3724x; 1.7079x over previous
#include <cuda_runtime.h>
#include <cuda_bf16.h>
#include <math.h>

#define BB 2
#define TT 2048
#define DIM 1024
#define HID 4096
#define NH 16
#define KVH 4
#define HD 64
#define WIN 512
#define MROWS (BB*TT)       // 4096
#define QKVN 1536

// ---------------- scratch ----------------
__device__ __nv_bfloat16 g_xnb[MROWS * DIM];
__device__ float         g_qkv[MROWS * QKVN];
__device__ __nv_bfloat16 g_qb [BB * NH  * TT * HD];
__device__ __nv_bfloat16 g_kb [BB * KVH * TT * HD];
__device__ __nv_bfloat16 g_vb [BB * KVH * TT * HD];
__device__ __nv_bfloat16 g_yb [MROWS * NH * HD];
__device__ float         g_h  [MROWS * DIM];
__device__ __nv_bfloat16 g_hnb[MROWS * DIM];
__device__ float         g_a1 [MROWS * HID];
__device__ __nv_bfloat16 g_gb [MROWS * HID];
__device__ __nv_bfloat16 g_wqkv[QKVN * DIM];
__device__ __nv_bfloat16 g_wob [DIM * NH * HD];
__device__ __nv_bfloat16 g_w1b [HID * DIM];
__device__ __nv_bfloat16 g_w3b [HID * DIM];
__device__ __nv_bfloat16 g_w2b [DIM * HID];

// ---------------- helpers ----------------
__device__ __forceinline__ void cp16(unsigned saddr, const void* g) {
    asm volatile("cp.async.cg.shared.global [%0], [%1], 16;\n" :: "r"(saddr), "l"(g));
}
__device__ __forceinline__ uint4 ldm_x4(unsigned addr) {
    uint4 r;
    asm volatile("ldmatrix.sync.aligned.m8n8.x4.shared.b16 {%0,%1,%2,%3}, [%4];\n"
                 : "=r"(r.x), "=r"(r.y), "=r"(r.z), "=r"(r.w) : "r"(addr));
    return r;
}
__device__ __forceinline__ uint4 ldm_x4t(unsigned addr) {
    uint4 r;
    asm volatile("ldmatrix.sync.aligned.m8n8.x4.trans.shared.b16 {%0,%1,%2,%3}, [%4];\n"
                 : "=r"(r.x), "=r"(r.y), "=r"(r.z), "=r"(r.w) : "r"(addr));
    return r;
}
__device__ __forceinline__ float ex2(float x) {
    float r; asm("ex2.approx.f32 %0, %1;" : "=f"(r) : "f"(x)); return r;
}
__device__ __forceinline__ void mma16816(
    float* c, unsigned a0, unsigned a1, unsigned a2, unsigned a3,
    unsigned b0, unsigned b1)
{
    asm volatile(
        "mma.sync.aligned.m16n8k16.row.col.f32.bf16.bf16.f32 "
        "{%0,%1,%2,%3}, {%4,%5,%6,%7}, {%8,%9}, {%0,%1,%2,%3};"
        : "+f"(c[0]), "+f"(c[1]), "+f"(c[2]), "+f"(c[3])
        : "r"(a0), "r"(a1), "r"(a2), "r"(a3), "r"(b0), "r"(b1));
}

// ---------------- fp32 -> bf16 convert ----------------
__global__ __launch_bounds__(256) void f2bf_kernel(
    const float* __restrict__ s, __nv_bfloat16* __restrict__ d, int n4)
{
    int i = blockIdx.x * 256 + threadIdx.x;
    if (i < n4) {
        float4 v = ((const float4*)s)[i];
        __nv_bfloat162 lo = __floats2bfloat162_rn(v.x, v.y);
        __nv_bfloat162 hi = __floats2bfloat162_rn(v.z, v.w);
        uint2 r; r.x = *(unsigned*)&lo; r.y = *(unsigned*)&hi;
        ((uint2*)d)[i] = r;
    }
}

// ---------------- RMSNorm over DIM=1024, bf16 out ----------------
__global__ __launch_bounds__(256) void rmsnorm_kernel(
    const float* __restrict__ x, const float* __restrict__ w,
    __nv_bfloat16* __restrict__ out, float eps)
{
    int row = blockIdx.x;
    int tid = threadIdx.x;
    const float4* xr = (const float4*)(x + (size_t)row * DIM);
    float4 xv = xr[tid];
    float acc = xv.x*xv.x + xv.y*xv.y + xv.z*xv.z + xv.w*xv.w;

    __shared__ float red[8];
    #pragma unroll
    for (int o = 16; o > 0; o >>= 1) acc += __shfl_xor_sync(0xffffffffu, acc, o);
    if ((tid & 31) == 0) red[tid >> 5] = acc;
    __syncthreads();
    if (tid < 8) {
        float a = red[tid];
        #pragma unroll
        for (int o = 4; o > 0; o >>= 1) a += __shfl_xor_sync(0xffu, a, o);
        if (tid == 0) red[0] = a;
    }
    __syncthreads();
    float r = rsqrtf(red[0] * (1.0f / DIM) + eps);

    float4 wv = ((const float4*)w)[tid];
    __nv_bfloat162 lo = __floats2bfloat162_rn(xv.x * r * wv.x, xv.y * r * wv.y);
    __nv_bfloat162 hi = __floats2bfloat162_rn(xv.z * r * wv.z, xv.w * r * wv.w);
    uint2 ov; ov.x = *(unsigned*)&lo; ov.y = *(unsigned*)&hi;
    ((uint2*)(out + (size_t)row * DIM))[tid] = ov;
}

// ---------------- pack q/k/v: headnorm (optional) + transpose + bf16 ----------------
// reads fused qkv fp32 [row][QKVN]; writes [b, head, t, HD] bf16.
// MODE 0: norm + extra scale (q), MODE 1: norm (k), MODE 2: copy (v)
template <int MODE>
__global__ __launch_bounds__(256) void pack_kernel(
    const float* __restrict__ qkv, const float* __restrict__ w,
    __nv_bfloat16* __restrict__ dst, int nh, int colOff, float xscale)
{
    int vec = blockIdx.x * 8 + (threadIdx.x >> 5);
    int lane = threadIdx.x & 31;
    int row = vec / nh, hh = vec % nh;       // row in [0, MROWS)
    int b = row / TT, t = row % TT;
    const float2* p = (const float2*)(qkv + (size_t)row * QKVN + colOff + hh * HD);
    float2 v = p[lane];
    float r = 1.0f;
    if (MODE < 2) {
        float acc = v.x * v.x + v.y * v.y;
        #pragma unroll
        for (int o = 16; o > 0; o >>= 1) acc += __shfl_xor_sync(0xffffffffu, acc, o);
        r = rsqrtf(acc * (1.0f / HD) + 1e-6f);
    }
    float2 wv;
    if (MODE < 2) wv = ((const float2*)w)[lane]; else { wv.x = 1.f; wv.y = 1.f; }
    float o0 = v.x * r * wv.x * xscale;
    float o1 = v.y * r * wv.y * xscale;
    __nv_bfloat162 ob = __floats2bfloat162_rn(o0, o1);
    *(__nv_bfloat162*)(dst + (((size_t)(b * nh + hh) * TT + t) * HD) + lane * 2) = ob;
}

// ---------------- bf16 GEMM, cp.async 3-stage + ldmatrix ----------------
#define STAGES 3
#define KT 64
#define PITCHB 144
#define PITCHW 36
#define OPBYTES (128 * PITCHB)
#define STAGE_BYTES (2 * OPBYTES)
#define GSMEM (STAGES * STAGE_BYTES)

template <int EPI>
__global__ __launch_bounds__(256) void gemm_kernel(
    const __nv_bfloat16* __restrict__ A, const __nv_bfloat16* __restrict__ W,
    void* __restrict__ Cv, int M, int N, int K,
    const float* __restrict__ res, const float* __restrict__ scale,
    const float* __restrict__ other)
{
    extern __shared__ char smem[];
    const int bm = blockIdx.y * 128;
    const int bn = blockIdx.x * 128;
    const int tid = threadIdx.x;
    const int warpId = tid >> 5, lane = tid & 31;
    const int gid = lane >> 2, tg = lane & 3;
    const int warpM = warpId & 1, warpN = warpId >> 1;
    const int r8 = lane & 7;

    const unsigned sbase = (unsigned)__cvta_generic_to_shared(smem);
    const int ktiles = K >> 6;

    float acc[4][4][4];
    #pragma unroll
    for (int mi = 0; mi < 4; mi++)
        #pragma unroll
        for (int ni = 0; ni < 4; ni++)
            #pragma unroll
            for (int c = 0; c < 4; c++) acc[mi][ni][c] = 0.f;

    auto fetch = [&](int s, int kt) {
        if (kt < ktiles) {
            unsigned sa = sbase + s * STAGE_BYTES;
            unsigned sb = sa + OPBYTES;
            #pragma unroll
            for (int i = 0; i < 4; i++) {
                int chunk = tid + i * 256;
                int row = chunk >> 3, c = chunk & 7;
                size_t go = (size_t)row * K + (size_t)kt * KT + c * 8;
                cp16(sa + row * PITCHB + c * 16, A + (size_t)bm * K + go);
                cp16(sb + row * PITCHB + c * 16, W + (size_t)bn * K + go);
            }
        }
    };

    // ldmatrix lane offsets
    unsigned aoff[4], boff[2];
    #pragma unroll
    for (int mi = 0; mi < 4; mi++)
        aoff[mi] = (warpM * 64 + mi * 16 + ((lane >> 3) & 1) * 8 + r8) * PITCHB + (lane >> 4) * 16;
    #pragma unroll
    for (int np = 0; np < 2; np++)
        boff[np] = (warpN * 32 + np * 16 + (lane >> 4) * 8 + r8) * PITCHB + ((lane >> 3) & 1) * 16;

    fetch(0, 0);
    asm volatile("cp.async.commit_group;\n" ::: "memory");
    fetch(1, 1);
    asm volatile("cp.async.commit_group;\n" ::: "memory");

    for (int kt = 0; kt < ktiles; kt++) {
        asm volatile("cp.async.wait_group 1;\n" ::: "memory");
        __syncthreads();

        fetch((kt + 2) % STAGES, kt + 2);
        asm volatile("cp.async.commit_group;\n" ::: "memory");

        const unsigned sa = sbase + (kt % STAGES) * STAGE_BYTES;
        const unsigned sb = sa + OPBYTES;

        #pragma unroll
        for (int ks = 0; ks < 4; ks++) {
            uint4 Af[4], Bf[2];
            #pragma unroll
            for (int mi = 0; mi < 4; mi++) Af[mi] = ldm_x4(sa + aoff[mi] + ks * 32);
            #pragma unroll
            for (int np = 0; np < 2; np++) Bf[np] = ldm_x4(sb + boff[np] + ks * 32);
            #pragma unroll
            for (int mi = 0; mi < 4; mi++) {
                mma16816(acc[mi][0], Af[mi].x, Af[mi].y, Af[mi].z, Af[mi].w, Bf[0].x, Bf[0].y);
                mma16816(acc[mi][1], Af[mi].x, Af[mi].y, Af[mi].z, Af[mi].w, Bf[0].z, Bf[0].w);
                mma16816(acc[mi][2], Af[mi].x, Af[mi].y, Af[mi].z, Af[mi].w, Bf[1].x, Bf[1].y);
                mma16816(acc[mi][3], Af[mi].x, Af[mi].y, Af[mi].z, Af[mi].w, Bf[1].z, Bf[1].w);
            }
        }
    }

    #pragma unroll
    for (int mi = 0; mi < 4; mi++) {
        #pragma unroll
        for (int ni = 0; ni < 4; ni++) {
            int m0 = bm + warpM * 64 + mi * 16 + gid;
            int n0 = bn + warpN * 32 + ni * 8 + tg * 2;
            #pragma unroll
            for (int half = 0; half < 2; half++) {
                int m = m0 + half * 8;
                size_t base = (size_t)m * N + n0;
                float v0 = acc[mi][ni][half * 2 + 0];
                float v1 = acc[mi][ni][half * 2 + 1];
                if (EPI == 0) {
                    float2 ov; ov.x = v0; ov.y = v1;
                    *(float2*)((float*)Cv + base) = ov;
                } else if (EPI == 1) {
                    v0 = res[base + 0] + v0 * scale[n0 + 0];
                    v1 = res[base + 1] + v1 * scale[n0 + 1];
                    float2 ov; ov.x = v0; ov.y = v1;
                    *(float2*)((float*)Cv + base) = ov;
                } else {
                    float a0 = other[base + 0];
                    float a1 = other[base + 1];
                    v0 = (a0 / (1.f + __expf(-a0))) * v0;
                    v1 = (a1 / (1.f + __expf(-a1))) * v1;
                    __nv_bfloat162 p = __floats2bfloat162_rn(v0, v1);
                    *(__nv_bfloat162*)((__nv_bfloat16*)Cv + base) = p;
                }
            }
        }
    }
}

// ---------------- MMA flash attention, sliding window, GQA ----------------
// block = 128 queries x 1 head; 8 warps x 16 rows; 64-key chunks, 2-stage cp.async.
#define ACK 64
#define APITCHB 144
#define AOP (ACK * APITCHB)      // 9216
#define ASTAGE (2 * AOP)         // K+V per stage

__global__ __launch_bounds__(256) void fattn_kernel(
    const __nv_bfloat16* __restrict__ qb, const __nv_bfloat16* __restrict__ kb,
    const __nv_bfloat16* __restrict__ vb, __nv_bfloat16* __restrict__ yb)
{
    __shared__ char asmem[2 * ASTAGE];   // 36864 B
    const int qt = blockIdx.x, bh = blockIdx.y;
    const int b = bh / NH, h = bh % NH;
    const int kvh = h / (NH / KVH);
    const int tid = threadIdx.x;
    const int w = tid >> 5, lane = tid & 31;
    const int gid = lane >> 2, tg = lane & 3;
    const int r8 = lane & 7;
    const int q0 = qt * 128;
    const int t0 = q0 + w * 16 + gid;
    const int t1 = t0 + 8;

    const unsigned sbase = (unsigned)__cvta_generic_to_shared(asmem);

    // Q fragments (bf16, pre-scaled by 0.125*log2e in pack)
    const __nv_bfloat16* qbase = qb + (size_t)(b * NH + h) * TT * HD;
    unsigned qa[4][4];
    #pragma unroll
    for (int kt = 0; kt < 4; kt++) {
        qa[kt][0] = *(const unsigned*)(qbase + (size_t)t0 * HD + kt * 16 + 2 * tg);
        qa[kt][1] = *(const unsigned*)(qbase + (size_t)t1 * HD + kt * 16 + 2 * tg);
        qa[kt][2] = *(const unsigned*)(qbase + (size_t)t0 * HD + kt * 16 + 8 + 2 * tg);
        qa[kt][3] = *(const unsigned*)(qbase + (size_t)t1 * HD + kt * 16 + 8 + 2 * tg);
    }

    float oacc[8][4];
    #pragma unroll
    for (int j = 0; j < 8; j++)
        #pragma unroll
        for (int c = 0; c < 4; c++) oacc[j][c] = 0.f;
    float m0 = -1e30f, m1 = -1e30f, l0 = 0.f, l1 = 0.f;

    const int kstart = max(0, q0 - WIN + 1) & ~(ACK - 1);
    const int nch = (q0 + 128 - kstart) / ACK;

    const __nv_bfloat16* kbase = kb + (size_t)(b * KVH + kvh) * TT * HD;
    const __nv_bfloat16* vbase = vb + (size_t)(b * KVH + kvh) * TT * HD;

    auto fetch = [&](int s, int kc) {
        unsigned sk = sbase + s * ASTAGE;
        unsigned sv = sk + AOP;
        #pragma unroll
        for (int i = 0; i < 2; i++) {
            int chunk = tid + i * 256;
            int row = chunk >> 3, c = chunk & 7;
            cp16(sk + row * APITCHB + c * 16, kbase + (size_t)(kc + row) * HD + c * 8);
            cp16(sv + row * APITCHB + c * 16, vbase + (size_t)(kc + row) * HD + c * 8);
        }
    };

    // ldmatrix lane offsets
    unsigned koff[4], voff0;
    #pragma unroll
    for (int np = 0; np < 4; np++)
        koff[np] = (np * 16 + (lane >> 4) * 8 + r8) * APITCHB + ((lane >> 3) & 1) * 16;
    voff0 = (((lane >> 3) & 1) * 8 + r8) * APITCHB + (lane >> 4) * 16;

    fetch(0, kstart);
    asm volatile("cp.async.commit_group;\n" ::: "memory");

    for (int ci = 0; ci < nch; ci++) {
        int kc = kstart + ci * ACK;
        bool more = (ci + 1 < nch);
        if (more) {
            fetch((ci + 1) & 1, kc + ACK);
            asm volatile("cp.async.commit_group;\n" ::: "memory");
            asm volatile("cp.async.wait_group 1;\n" ::: "memory");
        } else {
            asm volatile("cp.async.wait_group 0;\n" ::: "memory");
        }
        __syncthreads();

        const unsigned sk = sbase + (ci & 1) * ASTAGE;
        const unsigned sv = sk + AOP;

        // S = Q @ K^T
        float s[8][4];
        #pragma unroll
        for (int j = 0; j < 8; j++)
            #pragma unroll
            for (int c = 0; c < 4; c++) s[j][c] = 0.f;
        #pragma unroll
        for (int ks = 0; ks < 4; ks++) {
            #pragma unroll
            for (int np = 0; np < 4; np++) {
                uint4 Bf = ldm_x4(sk + koff[np] + ks * 32);
                mma16816(s[np * 2 + 0], qa[ks][0], qa[ks][1], qa[ks][2], qa[ks][3], Bf.x, Bf.y);
                mma16816(s[np * 2 + 1], qa[ks][0], qa[ks][1], qa[ks][2], qa[ks][3], Bf.z, Bf.w);
            }
        }

        // mask
        float cmax0 = -INFINITY, cmax1 = -INFINITY;
        #pragma unroll
        for (int j = 0; j < 8; j++) {
            int col = kc + j * 8 + 2 * tg;
            #pragma unroll
            for (int cc = 0; cc < 2; cc++) {
                int c0 = col + cc;
                if (!(c0 <= t0 && (t0 - c0) < WIN)) s[j][cc] = -INFINITY;
                if (!(c0 <= t1 && (t1 - c0) < WIN)) s[j][2 + cc] = -INFINITY;
            }
            cmax0 = fmaxf(cmax0, fmaxf(s[j][0], s[j][1]));
            cmax1 = fmaxf(cmax1, fmaxf(s[j][2], s[j][3]));
        }
        cmax0 = fmaxf(cmax0, __shfl_xor_sync(0xffffffffu, cmax0, 1));
        cmax0 = fmaxf(cmax0, __shfl_xor_sync(0xffffffffu, cmax0, 2));
        cmax1 = fmaxf(cmax1, __shfl_xor_sync(0xffffffffu, cmax1, 1));
        cmax1 = fmaxf(cmax1, __shfl_xor_sync(0xffffffffu, cmax1, 2));

        float nm0 = fmaxf(m0, cmax0), nm1 = fmaxf(m1, cmax1);
        float cr0 = ex2(m0 - nm0), cr1 = ex2(m1 - nm1);
        m0 = nm0; m1 = nm1;
        l0 *= cr0; l1 *= cr1;
        #pragma unroll
        for (int j = 0; j < 8; j++) {
            oacc[j][0] *= cr0; oacc[j][1] *= cr0;
            oacc[j][2] *= cr1; oacc[j][3] *= cr1;
        }
        #pragma unroll
        for (int j = 0; j < 8; j++) {
            s[j][0] = ex2(s[j][0] - nm0);
            s[j][1] = ex2(s[j][1] - nm0);
            s[j][2] = ex2(s[j][2] - nm1);
            s[j][3] = ex2(s[j][3] - nm1);
            l0 += s[j][0] + s[j][1];
            l1 += s[j][2] + s[j][3];
        }

        // O += P @ V
        #pragma unroll
        for (int kt = 0; kt < 4; kt++) {
            unsigned pa0, pa1, pa2, pa3;
            {
                __nv_bfloat162 t;
                t = __floats2bfloat162_rn(s[2*kt][0],   s[2*kt][1]);   pa0 = *(unsigned*)&t;
                t = __floats2bfloat162_rn(s[2*kt][2],   s[2*kt][3]);   pa1 = *(unsigned*)&t;
                t = __floats2bfloat162_rn(s[2*kt+1][0], s[2*kt+1][1]); pa2 = *(unsigned*)&t;
                t = __floats2bfloat162_rn(s[2*kt+1][2], s[2*kt+1][3]); pa3 = *(unsigned*)&t;
            }
            #pragma unroll
            for (int dp = 0; dp < 4; dp++) {
                uint4 Vf = ldm_x4t(sv + voff0 + kt * 16 * APITCHB + dp * 32);
                mma16816(oacc[dp * 2 + 0], pa0, pa1, pa2, pa3, Vf.x, Vf.y);
                mma16816(oacc[dp * 2 + 1], pa0, pa1, pa2, pa3, Vf.z, Vf.w);
            }
        }
        __syncthreads();
    }

    l0 += __shfl_xor_sync(0xffffffffu, l0, 1);
    l0 += __shfl_xor_sync(0xffffffffu, l0, 2);
    l1 += __shfl_xor_sync(0xffffffffu, l1, 1);
    l1 += __shfl_xor_sync(0xffffffffu, l1, 2);
    float inv0 = 1.f / l0, inv1 = 1.f / l1;

    #pragma unroll
    for (int j = 0; j < 8; j++) {
        int n0 = h * HD + j * 8 + 2 * tg;
        __nv_bfloat162 p0 = __floats2bfloat162_rn(oacc[j][0] * inv0, oacc[j][1] * inv0);
        __nv_bfloat162 p1 = __floats2bfloat162_rn(oacc[j][2] * inv1, oacc[j][3] * inv1);
        *(__nv_bfloat162*)(yb + (size_t)(b * TT + t0) * (NH * HD) + n0) = p0;
        *(__nv_bfloat162*)(yb + (size_t)(b * TT + t1) * (NH * HD) + n0) = p1;
    }
}

// ---------------- launch ----------------
extern "C" void kernel_launch(void* const* d_in, const int* in_sizes, int n_in,
                              void* d_out, int out_size)
{
    const float* x            = (const float*)d_in[0];
    const float* wq           = (const float*)d_in[1];
    const float* wk           = (const float*)d_in[2];
    const float* wv           = (const float*)d_in[3];
    const float* wo           = (const float*)d_in[4];
    const float* w1           = (const float*)d_in[5];
    const float* w2           = (const float*)d_in[6];
    const float* w3           = (const float*)d_in[7];
    const float* q_norm_w     = (const float*)d_in[8];
    const float* k_norm_w     = (const float*)d_in[9];
    const float* attn_norm_w  = (const float*)d_in[10];
    const float* ffn_norm_w   = (const float*)d_in[11];
    const float* attn_scale   = (const float*)d_in[12];
    const float* ffn_scale    = (const float*)d_in[13];
    float* out = (float*)d_out;

    __nv_bfloat16 *xnb, *qbp, *kbp, *vbp, *yb, *hnb, *gb, *wqkv, *wob, *w1b, *w3b, *w2b;
    float *qkv, *h, *a1;
    cudaGetSymbolAddress((void**)&xnb,  g_xnb);
    cudaGetSymbolAddress((void**)&qkv,  g_qkv);
    cudaGetSymbolAddress((void**)&qbp,  g_qb);
    cudaGetSymbolAddress((void**)&kbp,  g_kb);
    cudaGetSymbolAddress((void**)&vbp,  g_vb);
    cudaGetSymbolAddress((void**)&yb,   g_yb);
    cudaGetSymbolAddress((void**)&h,    g_h);
    cudaGetSymbolAddress((void**)&hnb,  g_hnb);
    cudaGetSymbolAddress((void**)&a1,   g_a1);
    cudaGetSymbolAddress((void**)&gb,   g_gb);
    cudaGetSymbolAddress((void**)&wqkv, g_wqkv);
    cudaGetSymbolAddress((void**)&wob,  g_wob);
    cudaGetSymbolAddress((void**)&w1b,  g_w1b);
    cudaGetSymbolAddress((void**)&w3b,  g_w3b);
    cudaGetSymbolAddress((void**)&w2b,  g_w2b);

    const int M = MROWS;
    const int smem_bytes = GSMEM;
    cudaFuncSetAttribute(gemm_kernel<0>, cudaFuncAttributeMaxDynamicSharedMemorySize, smem_bytes);
    cudaFuncSetAttribute(gemm_kernel<1>, cudaFuncAttributeMaxDynamicSharedMemorySize, smem_bytes);
    cudaFuncSetAttribute(gemm_kernel<2>, cudaFuncAttributeMaxDynamicSharedMemorySize, smem_bytes);

    // 0) weight conversions
    f2bf_kernel<<<(NH*HD*DIM)/4/256,  256>>>(wq, wqkv,                  (NH*HD*DIM)/4);
    f2bf_kernel<<<(KVH*HD*DIM)/4/256, 256>>>(wk, wqkv + NH*HD*DIM,      (KVH*HD*DIM)/4);
    f2bf_kernel<<<(KVH*HD*DIM)/4/256, 256>>>(wv, wqkv + (NH+KVH)*HD*DIM,(KVH*HD*DIM)/4);
    f2bf_kernel<<<(DIM*NH*HD)/4/256,  256>>>(wo, wob, (DIM*NH*HD)/4);
    f2bf_kernel<<<(HID*DIM)/4/256,    256>>>(w1, w1b, (HID*DIM)/4);
    f2bf_kernel<<<(HID*DIM)/4/256,    256>>>(w3, w3b, (HID*DIM)/4);
    f2bf_kernel<<<(DIM*HID)/4/256,    256>>>(w2, w2b, (DIM*HID)/4);

    // 1) attn pre-norm
    rmsnorm_kernel<<<M, 256>>>(x, attn_norm_w, xnb, 1e-5f);

    // 2) fused QKV projection (fp32 out)
    gemm_kernel<0><<<dim3(QKVN/128, M/128), 256, smem_bytes>>>(
        xnb, wqkv, qkv, M, QKVN, DIM, nullptr, nullptr, nullptr);

    // 3) pack q (norm + softmax scale in log2 domain), k (norm), v
    const float QSCALE = 0.125f * 1.4426950408889634f;
    pack_kernel<0><<<(M*NH)/8,  256>>>(qkv, q_norm_w, qbp, NH,  0,               QSCALE);
    pack_kernel<1><<<(M*KVH)/8, 256>>>(qkv, k_norm_w, kbp, KVH, NH*HD,           1.0f);
    pack_kernel<2><<<(M*KVH)/8, 256>>>(qkv, nullptr,  vbp, KVH, (NH+KVH)*HD,     1.0f);

    // 4) MMA flash attention
    fattn_kernel<<<dim3(TT / 128, BB * NH), 256>>>(qbp, kbp, vbp, yb);

    // 5) output projection + residual + layer scale -> h
    gemm_kernel<1><<<dim3(DIM/128, M/128), 256, smem_bytes>>>(
        yb, wob, h, M, DIM, NH*HD, x, attn_scale, nullptr);

    // 6) ffn pre-norm
    rmsnorm_kernel<<<M, 256>>>(h, ffn_norm_w, hnb, 1e-5f);

    // 7) SwiGLU FFN
    gemm_kernel<0><<<dim3(HID/128, M/128), 256, smem_bytes>>>(
        hnb, w1b, a1, M, HID, DIM, nullptr, nullptr, nullptr);
    gemm_kernel<2><<<dim3(HID/128, M/128), 256, smem_bytes>>>(
        hnb, w3b, gb, M, HID, DIM, nullptr, nullptr, a1);
    gemm_kernel<1><<<dim3(DIM/128, M/128), 256, smem_bytes>>>(
        gb, w2b, out, M, DIM, HID, h, ffn_scale, nullptr);
}